// round 4
// baseline (speedup 1.0000x reference)
#include <cuda_runtime.h>
#include <cuda_bf16.h>
#include <stdint.h>

#define N_NODES 100000
#define E_EDGES 1600000
#define DIN 128
#define HID 64
#define DOUT 2
#define SCAN_BLK 1024
#define NBLK_SCAN ((N_NODES + SCAN_BLK - 1) / SCAN_BLK)   // 98

// Scratch (device globals; no allocation allowed)
__device__ int    g_hist[N_NODES];
__device__ int    g_partial[256];
__device__ int    g_rowstart[N_NODES + 1];
__device__ int    g_cursor[N_NODES];
__device__ int2   g_perm[E_EDGES];                 // {edge, src} sorted by dst
__device__ float  g_agg0[(size_t)N_NODES * DIN];   // layer-0 MEAN aggregation
__device__ float  g_h[(size_t)N_NODES * HID];      // hidden activations
__device__ float4 g_tmp1[N_NODES];                 // {sum_p0, sum_p1, cnt, pad}

__device__ __forceinline__ void red_add_v4(float* addr, float a, float b, float c, float d) {
    asm volatile("red.global.add.v4.f32 [%0], {%1,%2,%3,%4};"
                 :: "l"(addr), "f"(a), "f"(b), "f"(c), "f"(d) : "memory");
}

// ---------------- binning: histogram over dst ----------------
__global__ void hist_kernel(const int* __restrict__ ei, int* __restrict__ hist, int E)
{
    int e = blockIdx.x * blockDim.x + threadIdx.x;
    if (e < E) atomicAdd(&hist[ei[E + e]], 1);
}

__global__ void blocksum_kernel(const int* __restrict__ hist, int* __restrict__ partial, int N)
{
    __shared__ int red[SCAN_BLK];
    int i = blockIdx.x * SCAN_BLK + threadIdx.x;
    red[threadIdx.x] = (i < N) ? hist[i] : 0;
    __syncthreads();
    for (int off = SCAN_BLK / 2; off > 0; off >>= 1) {
        if (threadIdx.x < off) red[threadIdx.x] += red[threadIdx.x + off];
        __syncthreads();
    }
    if (threadIdx.x == 0) partial[blockIdx.x] = red[0];
}

__global__ void scan_partials_kernel(int* __restrict__ partial, int nblk)
{
    __shared__ int sp[256];
    int t = threadIdx.x;
    if (t < nblk) sp[t] = partial[t];
    __syncthreads();
    if (t == 0) {
        int run = 0;
        for (int i = 0; i < nblk; i++) { int v = sp[i]; sp[i] = run; run += v; }
    }
    __syncthreads();
    if (t < nblk) partial[t] = sp[t];
}

__global__ void rowstart_kernel(const int* __restrict__ hist, const int* __restrict__ partial,
                                int* __restrict__ rowstart, int* __restrict__ cursor,
                                int N, int E)
{
    __shared__ int s[SCAN_BLK];
    int i = blockIdx.x * SCAN_BLK + threadIdx.x;
    int v = (i < N) ? hist[i] : 0;
    s[threadIdx.x] = v;
    __syncthreads();
    for (int off = 1; off < SCAN_BLK; off <<= 1) {
        int t = (threadIdx.x >= off) ? s[threadIdx.x - off] : 0;
        __syncthreads();
        s[threadIdx.x] += t;
        __syncthreads();
    }
    if (i < N) {
        int excl = s[threadIdx.x] - v + partial[blockIdx.x];
        rowstart[i] = excl;
        cursor[i]   = excl;
    }
    if (i == 0) rowstart[N] = E;
}

__global__ void build_kernel(const int* __restrict__ ei, int* __restrict__ cursor,
                             int2* __restrict__ perm, int E)
{
    int e = blockIdx.x * blockDim.x + threadIdx.x;
    if (e >= E) return;
    int s = ei[e];
    int d = ei[E + e];
    int pos = atomicAdd(&cursor[d], 1);
    perm[pos] = make_int2(e, s);
}

// ---------------- layer 0 aggregation: warp per dst, no atomics ----------------
__global__ void agg0_kernel(const float* __restrict__ x,
                            const float* __restrict__ ea,
                            const int2* __restrict__ perm,
                            const int* __restrict__ rowstart,
                            float* __restrict__ agg0,
                            int N)
{
    int warp = (blockIdx.x * blockDim.x + threadIdx.x) >> 5;
    int lane = threadIdx.x & 31;
    if (warp >= N) return;

    int beg = rowstart[warp];
    int end = rowstart[warp + 1];

    float4 acc = make_float4(0.f, 0.f, 0.f, 0.f);
    for (int base = beg; base < end; base += 32) {
        int take = min(end - base, 32);
        int2 p = make_int2(0, 0);
        if (lane < take) p = perm[base + lane];
        for (int j = 0; j < take; j++) {
            int e = __shfl_sync(0xFFFFFFFFu, p.x, j);
            int s = __shfl_sync(0xFFFFFFFFu, p.y, j);
            float4 ev = reinterpret_cast<const float4*>(ea + (long long)e * DIN)[lane];
            float4 xv = reinterpret_cast<const float4*>(x  + (long long)s * DIN)[lane];
            acc.x = fmaf(xv.x, ev.x, acc.x);
            acc.y = fmaf(xv.y, ev.y, acc.y);
            acc.z = fmaf(xv.z, ev.z, acc.z);
            acc.w = fmaf(xv.w, ev.w, acc.w);
        }
    }
    int deg = end - beg;
    float inv = (deg > 0) ? (1.0f / (float)deg) : 0.f;
    acc.x *= inv; acc.y *= inv; acc.z *= inv; acc.w *= inv;
    reinterpret_cast<float4*>(agg0 + (long long)warp * DIN)[lane] = acc;
}

// ---------------- layer 0 dense: h = relu(concat(x, agg0mean) @ W0 + b0) ----------------
__global__ void layer0_mm_kernel(const float* __restrict__ x,
                                 const float* __restrict__ agg0,
                                 const float* __restrict__ W0,
                                 const float* __restrict__ b0,
                                 float* __restrict__ h,
                                 int N)
{
    extern __shared__ float sm[];
    float* sW = sm;                 // 256*64
    float* sF = sm + 2 * DIN * HID; // 4*256

    for (int i = threadIdx.x; i < 2 * DIN * HID; i += blockDim.x)
        sW[i] = W0[i];
    __syncthreads();

    int slot = threadIdx.x >> 6;
    int oc   = threadIdx.x & 63;
    float bias = b0[oc];

    for (int base = blockIdx.x * 4; base < N; base += gridDim.x * 4) {
        __syncthreads();
        for (int i = threadIdx.x; i < 4 * 2 * DIN; i += blockDim.x) {
            int nn = base + (i >> 8);
            int k  = i & 255;
            float v = 0.f;
            if (nn < N) {
                if (k < DIN) v = x[(long long)nn * DIN + k];
                else         v = agg0[(long long)nn * DIN + (k - DIN)];
            }
            sF[i] = v;
        }
        __syncthreads();

        int node = base + slot;
        if (node < N) {
            const float* f = sF + slot * 2 * DIN;
            float acc = bias;
            #pragma unroll 8
            for (int k = 0; k < 2 * DIN; k++)
                acc = fmaf(f[k], sW[k * HID + oc], acc);
            h[(long long)node * HID + oc] = acc > 0.f ? acc : 0.f;
        }
    }
}

// ---------------- layer 1: project-then-scatter ----------------
// per edge: p[o] = sum_k (h[src][k] * ea1[e][k]) * W1[(64+k)][o]; red.v4 {p0,p1,1,0} -> tmp[dst]
__global__ void edgeproj1_kernel(const float* __restrict__ h,
                                 const int* __restrict__ ei,
                                 const float* __restrict__ ea,
                                 const float* __restrict__ W1,
                                 float4* __restrict__ tmp,
                                 int E)
{
    __shared__ float sw[2 * HID]; // W1 rows 64..127 (flat [128..255])
    if (threadIdx.x < 2 * HID) sw[threadIdx.x] = W1[2 * HID + threadIdx.x];
    __syncthreads();

    int warp = (blockIdx.x * blockDim.x + threadIdx.x) >> 5;
    int lane = threadIdx.x & 31;
    if (warp >= E) return;

    int s = ei[warp];
    int d = ei[E + warp];

    float2 hv = reinterpret_cast<const float2*>(h  + (long long)s * HID)[lane];
    float2 ev = reinterpret_cast<const float2*>(ea + (long long)warp * HID)[lane];
    float mx = hv.x * ev.x;
    float my = hv.y * ev.y;

    int k = 2 * lane;
    float a0 = mx * sw[k * 2 + 0] + my * sw[(k + 1) * 2 + 0];
    float a1 = mx * sw[k * 2 + 1] + my * sw[(k + 1) * 2 + 1];

    #pragma unroll
    for (int o = 16; o > 0; o >>= 1) {
        a0 += __shfl_xor_sync(0xFFFFFFFFu, a0, o);
        a1 += __shfl_xor_sync(0xFFFFFFFFu, a1, o);
    }
    if (lane == 0)
        red_add_v4(reinterpret_cast<float*>(tmp + d), a0, a1, 1.0f, 0.f);
}

// ---------------- layer 1 dense: out = h @ W1_top + tmp/cnt + b1 ----------------
__global__ void layer1_mm_kernel(const float* __restrict__ h,
                                 const float4* __restrict__ tmp,
                                 const float* __restrict__ W1,
                                 const float* __restrict__ b1,
                                 float* __restrict__ out,
                                 int N)
{
    __shared__ float sW[2 * HID]; // W1 rows 0..63 (flat [0..127])
    __shared__ float sb[DOUT];
    if (threadIdx.x < 2 * HID) sW[threadIdx.x] = W1[threadIdx.x];
    if (threadIdx.x < DOUT) sb[threadIdx.x] = b1[threadIdx.x];
    __syncthreads();

    int warp = (blockIdx.x * blockDim.x + threadIdx.x) >> 5;
    int lane = threadIdx.x & 31;
    if (warp >= N) return;

    long long rb = (long long)warp * HID;
    float h0 = h[rb + lane];
    float h1 = h[rb + 32 + lane];

    float acc0 = h0 * sW[lane * 2 + 0] + h1 * sW[(32 + lane) * 2 + 0];
    float acc1 = h0 * sW[lane * 2 + 1] + h1 * sW[(32 + lane) * 2 + 1];

    #pragma unroll
    for (int o = 16; o > 0; o >>= 1) {
        acc0 += __shfl_xor_sync(0xFFFFFFFFu, acc0, o);
        acc1 += __shfl_xor_sync(0xFFFFFFFFu, acc1, o);
    }
    if (lane == 0) {
        float4 t = tmp[warp];
        float inv = (t.z > 0.f) ? (1.0f / t.z) : 0.f;
        out[(long long)warp * DOUT + 0] = acc0 + t.x * inv + sb[0];
        out[(long long)warp * DOUT + 1] = acc1 + t.y * inv + sb[1];
    }
}

// ---------------------------------------------------------------------------
extern "C" void kernel_launch(void* const* d_in, const int* in_sizes, int n_in,
                              void* d_out, int out_size)
{
    const float* x   = (const float*)d_in[0];
    const int*   ei  = (const int*)d_in[1];
    const float* ea0 = (const float*)d_in[2];
    const float* ea1 = (const float*)d_in[3];
    const float* W0  = (const float*)d_in[4];
    const float* b0  = (const float*)d_in[5];
    const float* W1  = (const float*)d_in[6];
    const float* b1  = (const float*)d_in[7];
    float* out = (float*)d_out;

    const int N = in_sizes[0] / DIN;
    const int E = in_sizes[1] / 2;

    int *hist_p, *partial_p, *rowstart_p, *cursor_p;
    int2 *perm_p;
    float *agg0_p, *h_p;
    float4 *tmp1_p;
    cudaGetSymbolAddress((void**)&hist_p,     g_hist);
    cudaGetSymbolAddress((void**)&partial_p,  g_partial);
    cudaGetSymbolAddress((void**)&rowstart_p, g_rowstart);
    cudaGetSymbolAddress((void**)&cursor_p,   g_cursor);
    cudaGetSymbolAddress((void**)&perm_p,     g_perm);
    cudaGetSymbolAddress((void**)&agg0_p,     g_agg0);
    cudaGetSymbolAddress((void**)&h_p,        g_h);
    cudaGetSymbolAddress((void**)&tmp1_p,     g_tmp1);

    cudaMemsetAsync(hist_p, 0, (size_t)N * sizeof(int), 0);
    cudaMemsetAsync(tmp1_p, 0, (size_t)N * sizeof(float4), 0);

    // --- binning ---
    hist_kernel<<<(E + 255) / 256, 256>>>(ei, hist_p, E);
    blocksum_kernel<<<NBLK_SCAN, SCAN_BLK>>>(hist_p, partial_p, N);
    scan_partials_kernel<<<1, 128>>>(partial_p, NBLK_SCAN);
    rowstart_kernel<<<NBLK_SCAN, SCAN_BLK>>>(hist_p, partial_p, rowstart_p, cursor_p, N, E);
    build_kernel<<<(E + 255) / 256, 256>>>(ei, cursor_p, perm_p, E);

    // --- layer 0 ---
    agg0_kernel<<<(N * 32 + 255) / 256, 256>>>(x, ea0, perm_p, rowstart_p, agg0_p, N);
    {
        size_t smem = (size_t)(2 * DIN * HID + 4 * 2 * DIN) * sizeof(float);
        cudaFuncSetAttribute(layer0_mm_kernel,
                             cudaFuncAttributeMaxDynamicSharedMemorySize, (int)smem);
        layer0_mm_kernel<<<2048, 256, smem>>>(x, agg0_p, W0, b0, h_p, N);
    }

    // --- layer 1 ---
    edgeproj1_kernel<<<(E * 32 + 255) / 256, 256>>>(h_p, ei, ea1, W1, tmp1_p, E);
    layer1_mm_kernel<<<(N * 32 + 255) / 256, 256>>>(h_p, tmp1_p, W1, b1, out, N);
}

// round 5
// speedup vs baseline: 1.0482x; 1.0482x over previous
#include <cuda_runtime.h>
#include <cuda_bf16.h>
#include <stdint.h>

#define N_NODES 100000
#define E_EDGES 1600000
#define DIN 128
#define HID 64
#define DOUT 2
#define SCAN_BLK 1024
#define NBLK_SCAN ((N_NODES + SCAN_BLK - 1) / SCAN_BLK)   // 98

// Scratch (device globals; no allocation allowed)
__device__ int    g_hist[N_NODES];
__device__ int    g_partial[256];
__device__ int    g_rowstart[N_NODES + 1];
__device__ int    g_cursor[N_NODES];
__device__ int2   g_perm[E_EDGES];                 // {edge, src} sorted by dst
__device__ float  g_agg0[(size_t)N_NODES * DIN];   // layer-0 MEAN aggregation
__device__ float  g_h[(size_t)N_NODES * HID];      // hidden activations
__device__ float4 g_tmp1[N_NODES];                 // {sum_p0, sum_p1, cnt, pad}

__device__ __forceinline__ void red_add_v4(float* addr, float a, float b, float c, float d) {
    asm volatile("red.global.add.v4.f32 [%0], {%1,%2,%3,%4};"
                 :: "l"(addr), "f"(a), "f"(b), "f"(c), "f"(d) : "memory");
}

__device__ __forceinline__ float4 ldcs4(const float4* p) {
    float4 v;
    asm volatile("ld.global.cs.v4.f32 {%0,%1,%2,%3}, [%4];"
                 : "=f"(v.x), "=f"(v.y), "=f"(v.z), "=f"(v.w) : "l"(p));
    return v;
}

// ---------------- binning: histogram over dst ----------------
__global__ void hist_kernel(const int* __restrict__ ei, int* __restrict__ hist, int E)
{
    int e = blockIdx.x * blockDim.x + threadIdx.x;
    if (e < E) atomicAdd(&hist[ei[E + e]], 1);
}

__global__ void blocksum_kernel(const int* __restrict__ hist, int* __restrict__ partial, int N)
{
    __shared__ int red[SCAN_BLK];
    int i = blockIdx.x * SCAN_BLK + threadIdx.x;
    red[threadIdx.x] = (i < N) ? hist[i] : 0;
    __syncthreads();
    for (int off = SCAN_BLK / 2; off > 0; off >>= 1) {
        if (threadIdx.x < off) red[threadIdx.x] += red[threadIdx.x + off];
        __syncthreads();
    }
    if (threadIdx.x == 0) partial[blockIdx.x] = red[0];
}

__global__ void scan_partials_kernel(int* __restrict__ partial, int nblk)
{
    __shared__ int sp[256];
    int t = threadIdx.x;
    if (t < nblk) sp[t] = partial[t];
    __syncthreads();
    if (t == 0) {
        int run = 0;
        for (int i = 0; i < nblk; i++) { int v = sp[i]; sp[i] = run; run += v; }
    }
    __syncthreads();
    if (t < nblk) partial[t] = sp[t];
}

__global__ void rowstart_kernel(const int* __restrict__ hist, const int* __restrict__ partial,
                                int* __restrict__ rowstart, int* __restrict__ cursor,
                                int N, int E)
{
    __shared__ int s[SCAN_BLK];
    int i = blockIdx.x * SCAN_BLK + threadIdx.x;
    int v = (i < N) ? hist[i] : 0;
    s[threadIdx.x] = v;
    __syncthreads();
    for (int off = 1; off < SCAN_BLK; off <<= 1) {
        int t = (threadIdx.x >= off) ? s[threadIdx.x - off] : 0;
        __syncthreads();
        s[threadIdx.x] += t;
        __syncthreads();
    }
    if (i < N) {
        int excl = s[threadIdx.x] - v + partial[blockIdx.x];
        rowstart[i] = excl;
        cursor[i]   = excl;
    }
    if (i == 0) rowstart[N] = E;
}

__global__ void build_kernel(const int* __restrict__ ei, int* __restrict__ cursor,
                             int2* __restrict__ perm, int E)
{
    int e = blockIdx.x * blockDim.x + threadIdx.x;
    if (e >= E) return;
    int s = ei[e];
    int d = ei[E + e];
    int pos = atomicAdd(&cursor[d], 1);
    perm[pos] = make_int2(e, s);
}

// ---------------- layer 0 aggregation: warp per dst, 4-edge batched loads ----------------
__global__ void agg0_kernel(const float* __restrict__ x,
                            const float* __restrict__ ea,
                            const int2* __restrict__ perm,
                            const int* __restrict__ rowstart,
                            float* __restrict__ agg0,
                            int N)
{
    int warp = (blockIdx.x * blockDim.x + threadIdx.x) >> 5;
    int lane = threadIdx.x & 31;
    if (warp >= N) return;

    int beg = rowstart[warp];
    int end = rowstart[warp + 1];

    float4 acc = make_float4(0.f, 0.f, 0.f, 0.f);
    for (int base = beg; base < end; base += 32) {
        int take = min(end - base, 32);
        int2 p = make_int2(0, 0);
        if (lane < take) p = perm[base + lane];

        int j = 0;
        for (; j + 4 <= take; j += 4) {
            int e0 = __shfl_sync(0xFFFFFFFFu, p.x, j + 0);
            int s0 = __shfl_sync(0xFFFFFFFFu, p.y, j + 0);
            int e1 = __shfl_sync(0xFFFFFFFFu, p.x, j + 1);
            int s1 = __shfl_sync(0xFFFFFFFFu, p.y, j + 1);
            int e2 = __shfl_sync(0xFFFFFFFFu, p.x, j + 2);
            int s2 = __shfl_sync(0xFFFFFFFFu, p.y, j + 2);
            int e3 = __shfl_sync(0xFFFFFFFFu, p.x, j + 3);
            int s3 = __shfl_sync(0xFFFFFFFFu, p.y, j + 3);

            // 8 independent loads in flight before any FMA
            float4 ev0 = ldcs4(reinterpret_cast<const float4*>(ea + (long long)e0 * DIN) + lane);
            float4 ev1 = ldcs4(reinterpret_cast<const float4*>(ea + (long long)e1 * DIN) + lane);
            float4 ev2 = ldcs4(reinterpret_cast<const float4*>(ea + (long long)e2 * DIN) + lane);
            float4 ev3 = ldcs4(reinterpret_cast<const float4*>(ea + (long long)e3 * DIN) + lane);
            float4 xv0 = reinterpret_cast<const float4*>(x + (long long)s0 * DIN)[lane];
            float4 xv1 = reinterpret_cast<const float4*>(x + (long long)s1 * DIN)[lane];
            float4 xv2 = reinterpret_cast<const float4*>(x + (long long)s2 * DIN)[lane];
            float4 xv3 = reinterpret_cast<const float4*>(x + (long long)s3 * DIN)[lane];

            acc.x = fmaf(xv0.x, ev0.x, acc.x); acc.y = fmaf(xv0.y, ev0.y, acc.y);
            acc.z = fmaf(xv0.z, ev0.z, acc.z); acc.w = fmaf(xv0.w, ev0.w, acc.w);
            acc.x = fmaf(xv1.x, ev1.x, acc.x); acc.y = fmaf(xv1.y, ev1.y, acc.y);
            acc.z = fmaf(xv1.z, ev1.z, acc.z); acc.w = fmaf(xv1.w, ev1.w, acc.w);
            acc.x = fmaf(xv2.x, ev2.x, acc.x); acc.y = fmaf(xv2.y, ev2.y, acc.y);
            acc.z = fmaf(xv2.z, ev2.z, acc.z); acc.w = fmaf(xv2.w, ev2.w, acc.w);
            acc.x = fmaf(xv3.x, ev3.x, acc.x); acc.y = fmaf(xv3.y, ev3.y, acc.y);
            acc.z = fmaf(xv3.z, ev3.z, acc.z); acc.w = fmaf(xv3.w, ev3.w, acc.w);
        }
        for (; j < take; j++) {
            int e = __shfl_sync(0xFFFFFFFFu, p.x, j);
            int s = __shfl_sync(0xFFFFFFFFu, p.y, j);
            float4 ev = ldcs4(reinterpret_cast<const float4*>(ea + (long long)e * DIN) + lane);
            float4 xv = reinterpret_cast<const float4*>(x + (long long)s * DIN)[lane];
            acc.x = fmaf(xv.x, ev.x, acc.x);
            acc.y = fmaf(xv.y, ev.y, acc.y);
            acc.z = fmaf(xv.z, ev.z, acc.z);
            acc.w = fmaf(xv.w, ev.w, acc.w);
        }
    }
    int deg = end - beg;
    float inv = (deg > 0) ? (1.0f / (float)deg) : 0.f;
    acc.x *= inv; acc.y *= inv; acc.z *= inv; acc.w *= inv;
    reinterpret_cast<float4*>(agg0 + (long long)warp * DIN)[lane] = acc;
}

// ---------------- layer 0 dense: h = relu(concat(x, agg0mean) @ W0 + b0) ----------------
__global__ void layer0_mm_kernel(const float* __restrict__ x,
                                 const float* __restrict__ agg0,
                                 const float* __restrict__ W0,
                                 const float* __restrict__ b0,
                                 float* __restrict__ h,
                                 int N)
{
    extern __shared__ float sm[];
    float* sW = sm;                 // 256*64
    float* sF = sm + 2 * DIN * HID; // 4*256

    for (int i = threadIdx.x; i < 2 * DIN * HID; i += blockDim.x)
        sW[i] = W0[i];
    __syncthreads();

    int slot = threadIdx.x >> 6;
    int oc   = threadIdx.x & 63;
    float bias = b0[oc];

    for (int base = blockIdx.x * 4; base < N; base += gridDim.x * 4) {
        __syncthreads();
        for (int i = threadIdx.x; i < 4 * 2 * DIN; i += blockDim.x) {
            int nn = base + (i >> 8);
            int k  = i & 255;
            float v = 0.f;
            if (nn < N) {
                if (k < DIN) v = x[(long long)nn * DIN + k];
                else         v = agg0[(long long)nn * DIN + (k - DIN)];
            }
            sF[i] = v;
        }
        __syncthreads();

        int node = base + slot;
        if (node < N) {
            const float* f = sF + slot * 2 * DIN;
            float acc = bias;
            #pragma unroll 8
            for (int k = 0; k < 2 * DIN; k++)
                acc = fmaf(f[k], sW[k * HID + oc], acc);
            h[(long long)node * HID + oc] = acc > 0.f ? acc : 0.f;
        }
    }
}

// ---------------- layer 1: project-then-scatter ----------------
__global__ void edgeproj1_kernel(const float* __restrict__ h,
                                 const int* __restrict__ ei,
                                 const float* __restrict__ ea,
                                 const float* __restrict__ W1,
                                 float4* __restrict__ tmp,
                                 int E)
{
    __shared__ float sw[2 * HID]; // W1 rows 64..127 (flat [128..255])
    if (threadIdx.x < 2 * HID) sw[threadIdx.x] = W1[2 * HID + threadIdx.x];
    __syncthreads();

    int warp = (blockIdx.x * blockDim.x + threadIdx.x) >> 5;
    int lane = threadIdx.x & 31;
    if (warp >= E) return;

    int s = ei[warp];
    int d = ei[E + warp];

    float2 hv = reinterpret_cast<const float2*>(h  + (long long)s * HID)[lane];
    float2 ev = reinterpret_cast<const float2*>(ea + (long long)warp * HID)[lane];
    float mx = hv.x * ev.x;
    float my = hv.y * ev.y;

    int k = 2 * lane;
    float a0 = mx * sw[k * 2 + 0] + my * sw[(k + 1) * 2 + 0];
    float a1 = mx * sw[k * 2 + 1] + my * sw[(k + 1) * 2 + 1];

    #pragma unroll
    for (int o = 16; o > 0; o >>= 1) {
        a0 += __shfl_xor_sync(0xFFFFFFFFu, a0, o);
        a1 += __shfl_xor_sync(0xFFFFFFFFu, a1, o);
    }
    if (lane == 0)
        red_add_v4(reinterpret_cast<float*>(tmp + d), a0, a1, 1.0f, 0.f);
}

// ---------------- layer 1 dense: out = h @ W1_top + tmp/cnt + b1 ----------------
__global__ void layer1_mm_kernel(const float* __restrict__ h,
                                 const float4* __restrict__ tmp,
                                 const float* __restrict__ W1,
                                 const float* __restrict__ b1,
                                 float* __restrict__ out,
                                 int N)
{
    __shared__ float sW[2 * HID]; // W1 rows 0..63
    __shared__ float sb[DOUT];
    if (threadIdx.x < 2 * HID) sW[threadIdx.x] = W1[threadIdx.x];
    if (threadIdx.x < DOUT) sb[threadIdx.x] = b1[threadIdx.x];
    __syncthreads();

    int warp = (blockIdx.x * blockDim.x + threadIdx.x) >> 5;
    int lane = threadIdx.x & 31;
    if (warp >= N) return;

    long long rb = (long long)warp * HID;
    float h0 = h[rb + lane];
    float h1 = h[rb + 32 + lane];

    float acc0 = h0 * sW[lane * 2 + 0] + h1 * sW[(32 + lane) * 2 + 0];
    float acc1 = h0 * sW[lane * 2 + 1] + h1 * sW[(32 + lane) * 2 + 1];

    #pragma unroll
    for (int o = 16; o > 0; o >>= 1) {
        acc0 += __shfl_xor_sync(0xFFFFFFFFu, acc0, o);
        acc1 += __shfl_xor_sync(0xFFFFFFFFu, acc1, o);
    }
    if (lane == 0) {
        float4 t = tmp[warp];
        float inv = (t.z > 0.f) ? (1.0f / t.z) : 0.f;
        out[(long long)warp * DOUT + 0] = acc0 + t.x * inv + sb[0];
        out[(long long)warp * DOUT + 1] = acc1 + t.y * inv + sb[1];
    }
}

// ---------------------------------------------------------------------------
extern "C" void kernel_launch(void* const* d_in, const int* in_sizes, int n_in,
                              void* d_out, int out_size)
{
    const float* x   = (const float*)d_in[0];
    const int*   ei  = (const int*)d_in[1];
    const float* ea0 = (const float*)d_in[2];
    const float* ea1 = (const float*)d_in[3];
    const float* W0  = (const float*)d_in[4];
    const float* b0  = (const float*)d_in[5];
    const float* W1  = (const float*)d_in[6];
    const float* b1  = (const float*)d_in[7];
    float* out = (float*)d_out;

    const int N = in_sizes[0] / DIN;
    const int E = in_sizes[1] / 2;

    int *hist_p, *partial_p, *rowstart_p, *cursor_p;
    int2 *perm_p;
    float *agg0_p, *h_p;
    float4 *tmp1_p;
    cudaGetSymbolAddress((void**)&hist_p,     g_hist);
    cudaGetSymbolAddress((void**)&partial_p,  g_partial);
    cudaGetSymbolAddress((void**)&rowstart_p, g_rowstart);
    cudaGetSymbolAddress((void**)&cursor_p,   g_cursor);
    cudaGetSymbolAddress((void**)&perm_p,     g_perm);
    cudaGetSymbolAddress((void**)&agg0_p,     g_agg0);
    cudaGetSymbolAddress((void**)&h_p,        g_h);
    cudaGetSymbolAddress((void**)&tmp1_p,     g_tmp1);

    cudaMemsetAsync(hist_p, 0, (size_t)N * sizeof(int), 0);
    cudaMemsetAsync(tmp1_p, 0, (size_t)N * sizeof(float4), 0);

    // --- binning ---
    hist_kernel<<<(E + 255) / 256, 256>>>(ei, hist_p, E);
    blocksum_kernel<<<NBLK_SCAN, SCAN_BLK>>>(hist_p, partial_p, N);
    scan_partials_kernel<<<1, 128>>>(partial_p, NBLK_SCAN);
    rowstart_kernel<<<NBLK_SCAN, SCAN_BLK>>>(hist_p, partial_p, rowstart_p, cursor_p, N, E);
    build_kernel<<<(E + 255) / 256, 256>>>(ei, cursor_p, perm_p, E);

    // --- layer 0 ---
    agg0_kernel<<<(N * 32 + 255) / 256, 256>>>(x, ea0, perm_p, rowstart_p, agg0_p, N);
    {
        size_t smem = (size_t)(2 * DIN * HID + 4 * 2 * DIN) * sizeof(float);
        cudaFuncSetAttribute(layer0_mm_kernel,
                             cudaFuncAttributeMaxDynamicSharedMemorySize, (int)smem);
        layer0_mm_kernel<<<2048, 256, smem>>>(x, agg0_p, W0, b0, h_p, N);
    }

    // --- layer 1 ---
    edgeproj1_kernel<<<(E * 32 + 255) / 256, 256>>>(h_p, ei, ea1, W1, tmp1_p, E);
    layer1_mm_kernel<<<(N * 32 + 255) / 256, 256>>>(h_p, tmp1_p, W1, b1, out, N);
}

// round 6
// speedup vs baseline: 1.2181x; 1.1621x over previous
#include <cuda_runtime.h>
#include <cuda_bf16.h>
#include <stdint.h>

#define N_NODES 100000
#define E_EDGES 1600000
#define DIN 128
#define HID 64
#define DOUT 2

// Scratch (device globals; no allocation allowed)
__device__ int    g_hist[N_NODES];
__device__ int    g_rowstart[N_NODES + 1];
__device__ int    g_cursor[N_NODES];
__device__ int2   g_perm[E_EDGES];                 // {edge, src} sorted by dst
__device__ float  g_agg0[(size_t)N_NODES * DIN];   // layer-0 MEAN aggregation
__device__ float  g_h[(size_t)N_NODES * HID];      // hidden activations
__device__ float4 g_tmp1[N_NODES];                 // {sum_p0, sum_p1, cnt, pad}

__device__ __forceinline__ void red_add_v4(float* addr, float a, float b, float c, float d) {
    asm volatile("red.global.add.v4.f32 [%0], {%1,%2,%3,%4};"
                 :: "l"(addr), "f"(a), "f"(b), "f"(c), "f"(d) : "memory");
}

__device__ __forceinline__ float4 ldcs4(const float4* p) {
    float4 v;
    asm volatile("ld.global.cs.v4.f32 {%0,%1,%2,%3}, [%4];"
                 : "=f"(v.x), "=f"(v.y), "=f"(v.z), "=f"(v.w) : "l"(p));
    return v;
}

// ---------------- binning: histogram over dst ----------------
__global__ void hist_kernel(const int* __restrict__ ei, int* __restrict__ hist, int E)
{
    int e = blockIdx.x * blockDim.x + threadIdx.x;
    if (e < E) atomicAdd(&hist[ei[E + e]], 1);
}

// ---------------- single-block exclusive scan (shuffle-based, prefetch) ----------------
__global__ void scan_kernel(const int* __restrict__ hist,
                            int* __restrict__ rowstart, int* __restrict__ cursor,
                            int N, int E)
{
    __shared__ int warpsum[32];
    __shared__ int s_carry;
    int tid  = threadIdx.x;
    int lane = tid & 31;
    int wid  = tid >> 5;
    if (tid == 0) s_carry = 0;
    __syncthreads();

    int v = (tid < N) ? hist[tid] : 0;
    for (int base = 0; base < N; base += 1024) {
        // prefetch next tile
        int inext = base + 1024 + tid;
        int vnext = (inext < N && base + 1024 < N) ? hist[inext] : 0;

        // warp inclusive scan
        int incl = v;
        #pragma unroll
        for (int off = 1; off < 32; off <<= 1) {
            int t = __shfl_up_sync(0xFFFFFFFFu, incl, off);
            if (lane >= off) incl += t;
        }
        if (lane == 31) warpsum[wid] = incl;
        __syncthreads();
        if (wid == 0) {
            int w = (lane < 32) ? warpsum[lane] : 0;
            int wi = w;
            #pragma unroll
            for (int off = 1; off < 32; off <<= 1) {
                int t = __shfl_up_sync(0xFFFFFFFFu, wi, off);
                if (lane >= off) wi += t;
            }
            warpsum[lane] = wi - w;   // exclusive warp offsets
        }
        __syncthreads();
        int carry = s_carry;
        int excl = incl - v + warpsum[wid] + carry;
        int i = base + tid;
        if (i < N) { rowstart[i] = excl; cursor[i] = excl; }
        int blocktot = warpsum[31];
        // warpsum[31] is exclusive offset of last warp; need + its inclusive sum
        // simpler: total = excl_of_tid1023 + v_of_tid1023 broadcast:
        __syncthreads();
        if (tid == 1023) s_carry = excl + v - carry + carry; // = excl + v
        (void)blocktot;
        __syncthreads();
        v = vnext;
    }
    if (tid == 0) rowstart[N] = E;
}

__global__ void build_kernel(const int* __restrict__ ei, int* __restrict__ cursor,
                             int2* __restrict__ perm, int E)
{
    int e = blockIdx.x * blockDim.x + threadIdx.x;
    if (e >= E) return;
    int s = ei[e];
    int d = ei[E + e];
    int pos = atomicAdd(&cursor[d], 1);
    perm[pos] = make_int2(e, s);
}

// ---------------- layer 0 aggregation: warp per dst, 4-edge batched loads ----------------
__global__ void agg0_kernel(const float* __restrict__ x,
                            const float* __restrict__ ea,
                            const int2* __restrict__ perm,
                            const int* __restrict__ rowstart,
                            float* __restrict__ agg0,
                            int N)
{
    int warp = (blockIdx.x * blockDim.x + threadIdx.x) >> 5;
    int lane = threadIdx.x & 31;
    if (warp >= N) return;

    int beg = rowstart[warp];
    int end = rowstart[warp + 1];

    float4 acc = make_float4(0.f, 0.f, 0.f, 0.f);
    for (int base = beg; base < end; base += 32) {
        int take = min(end - base, 32);
        int2 p = make_int2(0, 0);
        if (lane < take) p = perm[base + lane];

        int j = 0;
        for (; j + 4 <= take; j += 4) {
            int e0 = __shfl_sync(0xFFFFFFFFu, p.x, j + 0);
            int s0 = __shfl_sync(0xFFFFFFFFu, p.y, j + 0);
            int e1 = __shfl_sync(0xFFFFFFFFu, p.x, j + 1);
            int s1 = __shfl_sync(0xFFFFFFFFu, p.y, j + 1);
            int e2 = __shfl_sync(0xFFFFFFFFu, p.x, j + 2);
            int s2 = __shfl_sync(0xFFFFFFFFu, p.y, j + 2);
            int e3 = __shfl_sync(0xFFFFFFFFu, p.x, j + 3);
            int s3 = __shfl_sync(0xFFFFFFFFu, p.y, j + 3);

            float4 ev0 = ldcs4(reinterpret_cast<const float4*>(ea + (long long)e0 * DIN) + lane);
            float4 ev1 = ldcs4(reinterpret_cast<const float4*>(ea + (long long)e1 * DIN) + lane);
            float4 ev2 = ldcs4(reinterpret_cast<const float4*>(ea + (long long)e2 * DIN) + lane);
            float4 ev3 = ldcs4(reinterpret_cast<const float4*>(ea + (long long)e3 * DIN) + lane);
            float4 xv0 = reinterpret_cast<const float4*>(x + (long long)s0 * DIN)[lane];
            float4 xv1 = reinterpret_cast<const float4*>(x + (long long)s1 * DIN)[lane];
            float4 xv2 = reinterpret_cast<const float4*>(x + (long long)s2 * DIN)[lane];
            float4 xv3 = reinterpret_cast<const float4*>(x + (long long)s3 * DIN)[lane];

            acc.x = fmaf(xv0.x, ev0.x, acc.x); acc.y = fmaf(xv0.y, ev0.y, acc.y);
            acc.z = fmaf(xv0.z, ev0.z, acc.z); acc.w = fmaf(xv0.w, ev0.w, acc.w);
            acc.x = fmaf(xv1.x, ev1.x, acc.x); acc.y = fmaf(xv1.y, ev1.y, acc.y);
            acc.z = fmaf(xv1.z, ev1.z, acc.z); acc.w = fmaf(xv1.w, ev1.w, acc.w);
            acc.x = fmaf(xv2.x, ev2.x, acc.x); acc.y = fmaf(xv2.y, ev2.y, acc.y);
            acc.z = fmaf(xv2.z, ev2.z, acc.z); acc.w = fmaf(xv2.w, ev2.w, acc.w);
            acc.x = fmaf(xv3.x, ev3.x, acc.x); acc.y = fmaf(xv3.y, ev3.y, acc.y);
            acc.z = fmaf(xv3.z, ev3.z, acc.z); acc.w = fmaf(xv3.w, ev3.w, acc.w);
        }
        for (; j < take; j++) {
            int e = __shfl_sync(0xFFFFFFFFu, p.x, j);
            int s = __shfl_sync(0xFFFFFFFFu, p.y, j);
            float4 ev = ldcs4(reinterpret_cast<const float4*>(ea + (long long)e * DIN) + lane);
            float4 xv = reinterpret_cast<const float4*>(x + (long long)s * DIN)[lane];
            acc.x = fmaf(xv.x, ev.x, acc.x);
            acc.y = fmaf(xv.y, ev.y, acc.y);
            acc.z = fmaf(xv.z, ev.z, acc.z);
            acc.w = fmaf(xv.w, ev.w, acc.w);
        }
    }
    int deg = end - beg;
    float inv = (deg > 0) ? (1.0f / (float)deg) : 0.f;
    acc.x *= inv; acc.y *= inv; acc.z *= inv; acc.w *= inv;
    reinterpret_cast<float4*>(agg0 + (long long)warp * DIN)[lane] = acc;
}

// ---------------- layer 0 dense: register-tiled GEMM ----------------
// Block: 64 nodes x 64 oc, 256 threads (16x16), each thread 4x4 outputs.
// smem: whole W0 [256][64] (64KB) + f-tile [64][256] (64KB).
__global__ void layer0_mm_kernel(const float* __restrict__ x,
                                 const float* __restrict__ agg0,
                                 const float* __restrict__ W0,
                                 const float* __restrict__ b0,
                                 float* __restrict__ h,
                                 int N)
{
    extern __shared__ float sm[];
    float* sW = sm;                   // [256][64]
    float* sF = sm + 2 * DIN * HID;   // [64][256]

    int tid = threadIdx.x;
    int to = tid & 15;   // oc group: oc = 4*to..4*to+3
    int tn = tid >> 4;   // node group: local nodes 4*tn..4*tn+3

    // stage W0 (float4, coalesced)
    {
        const float4* w4 = reinterpret_cast<const float4*>(W0);
        float4* sw4 = reinterpret_cast<float4*>(sW);
        for (int i = tid; i < 2 * DIN * HID / 4; i += 256) sw4[i] = w4[i];
    }

    int base = blockIdx.x * 64;

    // stage f-tile: 64 nodes x 256 k as float4 (node = idx/64, kq = idx%64)
    for (int idx = tid; idx < 64 * 64; idx += 256) {
        int node = base + (idx >> 6);
        int kq   = idx & 63;   // float4 index within 256 k
        float4 v = make_float4(0.f, 0.f, 0.f, 0.f);
        if (node < N) {
            if (kq < 32) v = reinterpret_cast<const float4*>(x    + (long long)node * DIN)[kq];
            else         v = reinterpret_cast<const float4*>(agg0 + (long long)node * DIN)[kq - 32];
        }
        reinterpret_cast<float4*>(sF + (idx >> 6) * 256)[kq] = v;
    }
    __syncthreads();

    float c[4][4];
    #pragma unroll
    for (int i = 0; i < 4; i++) {
        #pragma unroll
        for (int jj = 0; jj < 4; jj++) c[i][jj] = 0.f;
    }

    const float* fa0 = sF + (4 * tn + 0) * 256;
    const float* fa1 = sF + (4 * tn + 1) * 256;
    const float* fa2 = sF + (4 * tn + 2) * 256;
    const float* fa3 = sF + (4 * tn + 3) * 256;

    #pragma unroll 4
    for (int k = 0; k < 2 * DIN; k++) {
        float4 b = reinterpret_cast<const float4*>(sW + k * HID)[to];
        float a0 = fa0[k], a1 = fa1[k], a2 = fa2[k], a3 = fa3[k];
        c[0][0] = fmaf(a0, b.x, c[0][0]); c[0][1] = fmaf(a0, b.y, c[0][1]);
        c[0][2] = fmaf(a0, b.z, c[0][2]); c[0][3] = fmaf(a0, b.w, c[0][3]);
        c[1][0] = fmaf(a1, b.x, c[1][0]); c[1][1] = fmaf(a1, b.y, c[1][1]);
        c[1][2] = fmaf(a1, b.z, c[1][2]); c[1][3] = fmaf(a1, b.w, c[1][3]);
        c[2][0] = fmaf(a2, b.x, c[2][0]); c[2][1] = fmaf(a2, b.y, c[2][1]);
        c[2][2] = fmaf(a2, b.z, c[2][2]); c[2][3] = fmaf(a2, b.w, c[2][3]);
        c[3][0] = fmaf(a3, b.x, c[3][0]); c[3][1] = fmaf(a3, b.y, c[3][1]);
        c[3][2] = fmaf(a3, b.z, c[3][2]); c[3][3] = fmaf(a3, b.w, c[3][3]);
    }

    float4 bias = reinterpret_cast<const float4*>(b0)[to];
    #pragma unroll
    for (int i = 0; i < 4; i++) {
        int node = base + 4 * tn + i;
        if (node < N) {
            float4 o;
            o.x = fmaxf(c[i][0] + bias.x, 0.f);
            o.y = fmaxf(c[i][1] + bias.y, 0.f);
            o.z = fmaxf(c[i][2] + bias.z, 0.f);
            o.w = fmaxf(c[i][3] + bias.w, 0.f);
            reinterpret_cast<float4*>(h + (long long)node * HID)[to] = o;
        }
    }
}

// ---------------- layer 1: project-then-scatter ----------------
__global__ void edgeproj1_kernel(const float* __restrict__ h,
                                 const int* __restrict__ ei,
                                 const float* __restrict__ ea,
                                 const float* __restrict__ W1,
                                 float4* __restrict__ tmp,
                                 int E)
{
    __shared__ float sw[2 * HID]; // W1 rows 64..127 (flat [128..255])
    if (threadIdx.x < 2 * HID) sw[threadIdx.x] = W1[2 * HID + threadIdx.x];
    __syncthreads();

    int warp = (blockIdx.x * blockDim.x + threadIdx.x) >> 5;
    int lane = threadIdx.x & 31;
    if (warp >= E) return;

    int s = ei[warp];
    int d = ei[E + warp];

    float2 hv = reinterpret_cast<const float2*>(h  + (long long)s * HID)[lane];
    float2 ev = reinterpret_cast<const float2*>(ea + (long long)warp * HID)[lane];
    float mx = hv.x * ev.x;
    float my = hv.y * ev.y;

    int k = 2 * lane;
    float a0 = mx * sw[k * 2 + 0] + my * sw[(k + 1) * 2 + 0];
    float a1 = mx * sw[k * 2 + 1] + my * sw[(k + 1) * 2 + 1];

    #pragma unroll
    for (int o = 16; o > 0; o >>= 1) {
        a0 += __shfl_xor_sync(0xFFFFFFFFu, a0, o);
        a1 += __shfl_xor_sync(0xFFFFFFFFu, a1, o);
    }
    if (lane == 0)
        red_add_v4(reinterpret_cast<float*>(tmp + d), a0, a1, 1.0f, 0.f);
}

// ---------------- layer 1 dense: out = h @ W1_top + tmp/cnt + b1 ----------------
__global__ void layer1_mm_kernel(const float* __restrict__ h,
                                 const float4* __restrict__ tmp,
                                 const float* __restrict__ W1,
                                 const float* __restrict__ b1,
                                 float* __restrict__ out,
                                 int N)
{
    __shared__ float sW[2 * HID];
    __shared__ float sb[DOUT];
    if (threadIdx.x < 2 * HID) sW[threadIdx.x] = W1[threadIdx.x];
    if (threadIdx.x < DOUT) sb[threadIdx.x] = b1[threadIdx.x];
    __syncthreads();

    int warp = (blockIdx.x * blockDim.x + threadIdx.x) >> 5;
    int lane = threadIdx.x & 31;
    if (warp >= N) return;

    long long rb = (long long)warp * HID;
    float h0 = h[rb + lane];
    float h1 = h[rb + 32 + lane];

    float acc0 = h0 * sW[lane * 2 + 0] + h1 * sW[(32 + lane) * 2 + 0];
    float acc1 = h0 * sW[lane * 2 + 1] + h1 * sW[(32 + lane) * 2 + 1];

    #pragma unroll
    for (int o = 16; o > 0; o >>= 1) {
        acc0 += __shfl_xor_sync(0xFFFFFFFFu, acc0, o);
        acc1 += __shfl_xor_sync(0xFFFFFFFFu, acc1, o);
    }
    if (lane == 0) {
        float4 t = tmp[warp];
        float inv = (t.z > 0.f) ? (1.0f / t.z) : 0.f;
        out[(long long)warp * DOUT + 0] = acc0 + t.x * inv + sb[0];
        out[(long long)warp * DOUT + 1] = acc1 + t.y * inv + sb[1];
    }
}

// ---------------------------------------------------------------------------
extern "C" void kernel_launch(void* const* d_in, const int* in_sizes, int n_in,
                              void* d_out, int out_size)
{
    const float* x   = (const float*)d_in[0];
    const int*   ei  = (const int*)d_in[1];
    const float* ea0 = (const float*)d_in[2];
    const float* ea1 = (const float*)d_in[3];
    const float* W0  = (const float*)d_in[4];
    const float* b0  = (const float*)d_in[5];
    const float* W1  = (const float*)d_in[6];
    const float* b1  = (const float*)d_in[7];
    float* out = (float*)d_out;

    const int N = in_sizes[0] / DIN;
    const int E = in_sizes[1] / 2;

    int *hist_p, *rowstart_p, *cursor_p;
    int2 *perm_p;
    float *agg0_p, *h_p;
    float4 *tmp1_p;
    cudaGetSymbolAddress((void**)&hist_p,     g_hist);
    cudaGetSymbolAddress((void**)&rowstart_p, g_rowstart);
    cudaGetSymbolAddress((void**)&cursor_p,   g_cursor);
    cudaGetSymbolAddress((void**)&perm_p,     g_perm);
    cudaGetSymbolAddress((void**)&agg0_p,     g_agg0);
    cudaGetSymbolAddress((void**)&h_p,        g_h);
    cudaGetSymbolAddress((void**)&tmp1_p,     g_tmp1);

    // launches 0,1: memsets
    cudaMemsetAsync(hist_p, 0, (size_t)N * sizeof(int), 0);
    cudaMemsetAsync(tmp1_p, 0, (size_t)N * sizeof(float4), 0);

    // launch 2: histogram
    hist_kernel<<<(E + 255) / 256, 256>>>(ei, hist_p, E);
    // launch 3: fused single-block scan
    scan_kernel<<<1, 1024>>>(hist_p, rowstart_p, cursor_p, N, E);
    // launch 4: perm build
    build_kernel<<<(E + 255) / 256, 256>>>(ei, cursor_p, perm_p, E);

    // launch 5: agg0 (profiled by ncu -s 5 -c 1)
    agg0_kernel<<<(N * 32 + 255) / 256, 256>>>(x, ea0, perm_p, rowstart_p, agg0_p, N);

    // launch 6: layer0 tiled GEMM
    {
        size_t smem = (size_t)(2 * DIN * HID + 64 * 2 * DIN) * sizeof(float); // 128KB
        cudaFuncSetAttribute(layer0_mm_kernel,
                             cudaFuncAttributeMaxDynamicSharedMemorySize, (int)smem);
        layer0_mm_kernel<<<(N + 63) / 64, 256, smem>>>(x, agg0_p, W0, b0, h_p, N);
    }

    // launch 7: layer-1 edge projection + scatter
    edgeproj1_kernel<<<(E * 32 + 255) / 256, 256>>>(h_p, ei, ea1, W1, tmp1_p, E);
    // launch 8: layer-1 dense
    layer1_mm_kernel<<<(N * 32 + 255) / 256, 256>>>(h_p, tmp1_p, W1, b1, out, N);
}